// round 1
// baseline (speedup 1.0000x reference)
#include <cuda_runtime.h>
#include <math.h>

#define D_DIM 2048
#define N_DIM 4096

// Scratch (allocation-free rule: device globals)
__device__ float g_K[(size_t)N_DIM * D_DIM];   // 32 MB
__device__ float g_V[(size_t)N_DIM * D_DIM];   // 32 MB
__device__ float g_M[(size_t)D_DIM * D_DIM];   // 16 MB
__device__ float g_P[(size_t)D_DIM * D_DIM];   // 16 MB
__device__ float g_r[D_DIM];

// ---------------------------------------------------------------------------
// Generic tiled SGEMM: C[M,Nc] = alpha * op(A) @ op(B) (+ bias[col])
//   !TA: A stored row-major (M, Kd)     TA: A stored row-major (Kd, M)
//   !TB: B stored row-major (Kd, Nc)    TB: B stored row-major (Nc, Kd)
// BM=BN=128, BK=8, 256 threads, 8x8 per thread. All dims multiples of 128.
// ---------------------------------------------------------------------------
template<bool TA, bool TB, bool BIAS>
__global__ __launch_bounds__(256, 2)
void gemm128(const float* __restrict__ A, const float* __restrict__ B,
             const float* __restrict__ bias, float* __restrict__ C,
             int M, int Nc, int Kd, float alpha)
{
    __shared__ float As[8][128];
    __shared__ float Bs[8][128];

    const int tid = threadIdx.x;
    const int bm0 = blockIdx.y * 128;
    const int bn0 = blockIdx.x * 128;

    const int ty = tid >> 4;    // 0..15 (row group)
    const int tx = tid & 15;    // 0..15 (col group)

    float acc[8][8];
    #pragma unroll
    for (int i = 0; i < 8; i++)
        #pragma unroll
        for (int j = 0; j < 8; j++) acc[i][j] = 0.0f;

    for (int k0 = 0; k0 < Kd; k0 += 8) {
        // ---- load A tile into As[k][m] ----
        if (!TA) {
            const int row = tid >> 1;           // 0..127 (m within tile)
            const int kq  = (tid & 1) * 4;      // 0 or 4
            float4 f = *reinterpret_cast<const float4*>(
                &A[(size_t)(bm0 + row) * Kd + k0 + kq]);
            As[kq + 0][row] = f.x; As[kq + 1][row] = f.y;
            As[kq + 2][row] = f.z; As[kq + 3][row] = f.w;
        } else {
            const int kr = tid >> 5;            // 0..7
            const int mq = (tid & 31) * 4;      // 0..124
            float4 f = *reinterpret_cast<const float4*>(
                &A[(size_t)(k0 + kr) * M + bm0 + mq]);
            *reinterpret_cast<float4*>(&As[kr][mq]) = f;
        }
        // ---- load B tile into Bs[k][n] ----
        if (!TB) {
            const int kr = tid >> 5;
            const int nq = (tid & 31) * 4;
            float4 f = *reinterpret_cast<const float4*>(
                &B[(size_t)(k0 + kr) * Nc + bn0 + nq]);
            *reinterpret_cast<float4*>(&Bs[kr][nq]) = f;
        } else {
            const int row = tid >> 1;           // n within tile
            const int kq  = (tid & 1) * 4;
            float4 f = *reinterpret_cast<const float4*>(
                &B[(size_t)(bn0 + row) * Kd + k0 + kq]);
            Bs[kq + 0][row] = f.x; Bs[kq + 1][row] = f.y;
            Bs[kq + 2][row] = f.z; Bs[kq + 3][row] = f.w;
        }
        __syncthreads();

        #pragma unroll
        for (int kk = 0; kk < 8; kk++) {
            float a[8], b[8];
            *reinterpret_cast<float4*>(&a[0]) =
                *reinterpret_cast<const float4*>(&As[kk][ty * 8 + 0]);
            *reinterpret_cast<float4*>(&a[4]) =
                *reinterpret_cast<const float4*>(&As[kk][ty * 8 + 4]);
            *reinterpret_cast<float4*>(&b[0]) =
                *reinterpret_cast<const float4*>(&Bs[kk][tx * 8 + 0]);
            *reinterpret_cast<float4*>(&b[4]) =
                *reinterpret_cast<const float4*>(&Bs[kk][tx * 8 + 4]);
            #pragma unroll
            for (int i = 0; i < 8; i++)
                #pragma unroll
                for (int j = 0; j < 8; j++)
                    acc[i][j] = fmaf(a[i], b[j], acc[i][j]);
        }
        __syncthreads();
    }

    // ---- epilogue ----
    #pragma unroll
    for (int i = 0; i < 8; i++) {
        const int gr = bm0 + ty * 8 + i;
        #pragma unroll
        for (int j = 0; j < 8; j += 4) {
            const int gc = bn0 + tx * 8 + j;
            float4 o;
            o.x = alpha * acc[i][j + 0];
            o.y = alpha * acc[i][j + 1];
            o.z = alpha * acc[i][j + 2];
            o.w = alpha * acc[i][j + 3];
            if (BIAS) {
                o.x += bias[gc + 0]; o.y += bias[gc + 1];
                o.z += bias[gc + 2]; o.w += bias[gc + 3];
            }
            *reinterpret_cast<float4*>(&C[(size_t)gr * Nc + gc]) = o;
        }
    }
}

// r[j] = scale * sum_i bq[i] * M[i, j]   (exact bq handling; bq==0 in dataset)
__global__ void bias_row_kernel(const float* __restrict__ bq,
                                const float* __restrict__ Mmat,
                                float* __restrict__ r, float scale)
{
    const int j = blockIdx.x * blockDim.x + threadIdx.x;
    if (j >= D_DIM) return;
    float s = 0.0f;
    #pragma unroll 8
    for (int i = 0; i < D_DIM; i++)
        s = fmaf(bq[i], Mmat[(size_t)i * D_DIM + j], s);
    r[j] = s * scale;
}

extern "C" void kernel_launch(void* const* d_in, const int* in_sizes, int n_in,
                              void* d_out, int out_size)
{
    const float* x  = (const float*)d_in[0];
    const float* Wq = (const float*)d_in[1];
    const float* bq = (const float*)d_in[2];
    const float* Wk = (const float*)d_in[3];
    const float* bk = (const float*)d_in[4];
    const float* Wv = (const float*)d_in[5];
    const float* bv = (const float*)d_in[6];
    float* out = (float*)d_out;

    float *pK, *pV, *pM, *pP, *pr;
    cudaGetSymbolAddress((void**)&pK, g_K);
    cudaGetSymbolAddress((void**)&pV, g_V);
    cudaGetSymbolAddress((void**)&pM, g_M);
    cudaGetSymbolAddress((void**)&pP, g_P);
    cudaGetSymbolAddress((void**)&pr, g_r);

    const float scale = 1.0f / sqrtf((float)D_DIM);

    dim3 blk(256);
    dim3 gridND(D_DIM / 128, N_DIM / 128);  // (16, 32)
    dim3 gridDD(D_DIM / 128, D_DIM / 128);  // (16, 16)

    // 1) K = x @ Wk^T + bk   (NT)
    gemm128<false, true, true><<<gridND, blk>>>(x, Wk, bk, pK, N_DIM, D_DIM, D_DIM, 1.0f);
    // 2) V = x @ Wv^T + bv   (NT)
    gemm128<false, true, true><<<gridND, blk>>>(x, Wv, bv, pV, N_DIM, D_DIM, D_DIM, 1.0f);
    // 3) M = K^T @ V         (TN, Kd = N)
    gemm128<true, false, false><<<gridDD, blk>>>(pK, pV, nullptr, pM, D_DIM, D_DIM, N_DIM, 1.0f);
    // 4) P = scale * Wq^T @ M (TN)
    gemm128<true, false, false><<<gridDD, blk>>>(Wq, pM, nullptr, pP, D_DIM, D_DIM, D_DIM, scale);
    // 5) r = scale * bq^T @ M
    bias_row_kernel<<<D_DIM / 256, 256>>>(bq, pM, pr, scale);
    // 6) out = x @ P + r     (NN)
    gemm128<false, false, true><<<gridND, blk>>>(x, pP, pr, out, N_DIM, D_DIM, D_DIM, 1.0f);
}

// round 3
// speedup vs baseline: 2.3518x; 2.3518x over previous
#include <cuda_runtime.h>
#include <cuda_bf16.h>
#include <math.h>
#include <stdint.h>

#define D_DIM 2048
#define N_TOK 4096

// ---------------- device scratch (allocation-free rule) ----------------
__device__ __align__(128) __nv_bfloat16 g_x_hi [(size_t)N_TOK * D_DIM];
__device__ __align__(128) __nv_bfloat16 g_x_lo [(size_t)N_TOK * D_DIM];
__device__ __align__(128) __nv_bfloat16 g_wk_hi[(size_t)D_DIM * D_DIM];
__device__ __align__(128) __nv_bfloat16 g_wk_lo[(size_t)D_DIM * D_DIM];
__device__ __align__(128) __nv_bfloat16 g_wv_hi[(size_t)D_DIM * D_DIM];
__device__ __align__(128) __nv_bfloat16 g_wv_lo[(size_t)D_DIM * D_DIM];
__device__ __align__(128) __nv_bfloat16 g_wqT_hi[(size_t)D_DIM * D_DIM];
__device__ __align__(128) __nv_bfloat16 g_wqT_lo[(size_t)D_DIM * D_DIM];
__device__ __align__(128) __nv_bfloat16 g_kt_hi[(size_t)D_DIM * N_TOK];
__device__ __align__(128) __nv_bfloat16 g_kt_lo[(size_t)D_DIM * N_TOK];
__device__ __align__(128) __nv_bfloat16 g_vt_hi[(size_t)D_DIM * N_TOK];
__device__ __align__(128) __nv_bfloat16 g_vt_lo[(size_t)D_DIM * N_TOK];
__device__ __align__(128) __nv_bfloat16 g_mt_hi[(size_t)D_DIM * D_DIM];
__device__ __align__(128) __nv_bfloat16 g_mt_lo[(size_t)D_DIM * D_DIM];
__device__ __align__(128) __nv_bfloat16 g_pt_hi[(size_t)D_DIM * D_DIM];
__device__ __align__(128) __nv_bfloat16 g_pt_lo[(size_t)D_DIM * D_DIM];
__device__ float g_r[D_DIM];

// ---------------- helpers ----------------
__device__ __forceinline__ uint32_t s2u(const void* p) {
    uint32_t a;
    asm("{ .reg .u64 t; cvta.to.shared.u64 t, %1; cvt.u32.u64 %0, t; }" : "=r"(a) : "l"(p));
    return a;
}
__device__ __forceinline__ void cp16(uint32_t dst, const void* src) {
    asm volatile("cp.async.cg.shared.global [%0], [%1], 16;" :: "r"(dst), "l"(src) : "memory");
}
__device__ __forceinline__ void cp_commit() {
    asm volatile("cp.async.commit_group;" ::: "memory");
}
template<int N>
__device__ __forceinline__ void cp_wait() {
    asm volatile("cp.async.wait_group %0;" :: "n"(N) : "memory");
}
__device__ __forceinline__ void ldsm4(uint32_t* r, uint32_t addr) {
    asm volatile("ldmatrix.sync.aligned.m8n8.x4.shared.b16 {%0,%1,%2,%3}, [%4];"
                 : "=r"(r[0]), "=r"(r[1]), "=r"(r[2]), "=r"(r[3]) : "r"(addr));
}
__device__ __forceinline__ void mma16816(float* d, const uint32_t* a, uint32_t b0, uint32_t b1) {
    asm volatile(
        "mma.sync.aligned.m16n8k16.row.col.f32.bf16.bf16.f32 "
        "{%0,%1,%2,%3}, {%4,%5,%6,%7}, {%8,%9}, {%0,%1,%2,%3};"
        : "+f"(d[0]), "+f"(d[1]), "+f"(d[2]), "+f"(d[3])
        : "r"(a[0]), "r"(a[1]), "r"(a[2]), "r"(a[3]), "r"(b0), "r"(b1));
}

// ---------------- split-bf16 HMMA GEMM ----------------
// C[m,n] = alpha * sum_k (Ah+Al)[m,k] * (Bh+Bl)[n,k]   (drops lo*lo)
// FINAL=false: Ch/Cl[n*Mtot + m] = split(C + bias[n])   (transposed split store)
// FINAL=true : Cf[m*Ntot + n]    = C*alpha + bias[n]    (fp32 row-major)
//
// Tile 128x128, BK=32. smem plane = 128 rows x 80B (64B data + 16B pad).
// Planes per stage: Ah(0) Al(1) Bh(2) Bl(3). Stage = 40960B, 2 stages.
#define PLANE_B 10240
#define STAGE_B 40960
static const int SMEM_DYN = 2 * STAGE_B;

template<bool FINAL>
__global__ void __launch_bounds__(256, 2) gemm_mma(
    const __nv_bfloat16* __restrict__ Ah, const __nv_bfloat16* __restrict__ Al,
    const __nv_bfloat16* __restrict__ Bh, const __nv_bfloat16* __restrict__ Bl,
    const float* __restrict__ bias,
    __nv_bfloat16* __restrict__ Ch, __nv_bfloat16* __restrict__ Cl,
    float* __restrict__ Cf,
    int Mtot, int Ntot, int Kd, float alpha)
{
    extern __shared__ char dyn[];
    const uint32_t su = s2u(dyn);
    const int tid  = threadIdx.x;
    const int wid  = tid >> 5, lane = tid & 31;
    const int bm0  = blockIdx.y * 128;
    const int bn0  = blockIdx.x * 128;
    const int wm0  = (wid & 1) * 64;   // warp m offset within tile
    const int wn0  = (wid >> 1) * 32;  // warp n offset within tile

    // ---- cp.async schedule: 2048 16B transfers / 256 threads = 8 each ----
    const __nv_bfloat16* gsrc[8];
    uint32_t doff[8];
    #pragma unroll
    for (int i = 0; i < 8; ++i) {
        int idx   = i * 256 + tid;
        int plane = idx >> 9;           // 0..3
        int row   = (idx >> 2) & 127;
        int seg   = idx & 3;
        const __nv_bfloat16* base =
            (plane == 0) ? Ah : (plane == 1) ? Al : (plane == 2) ? Bh : Bl;
        int grow = (plane < 2 ? bm0 : bn0) + row;
        gsrc[i] = base + (size_t)grow * Kd + seg * 8;
        doff[i] = (uint32_t)(plane * PLANE_B + row * 80 + seg * 16);
    }

    const int NC = Kd / 32;
    // prologue: stage 0
    #pragma unroll
    for (int i = 0; i < 8; ++i) cp16(su + doff[i], gsrc[i]);
    cp_commit();

    float acc[4][4][4];
    #pragma unroll
    for (int im = 0; im < 4; ++im)
        #pragma unroll
        for (int in = 0; in < 4; ++in)
            #pragma unroll
            for (int j = 0; j < 4; ++j) acc[im][in][j] = 0.0f;

    // lane parts for ldmatrix addressing
    const int a_rl = ((lane >> 3) & 1) * 8 + (lane & 7);   // row within m16
    const int a_ch = ((lane >> 4) & 1) * 16;               // 0 or 16 bytes (k half)
    const int b_rl = lane;                                 // row within n32

    for (int c = 0; c < NC; ++c) {
        cp_wait<0>();
        __syncthreads();
        if (c + 1 < NC) {
            const uint32_t sd = su + ((c + 1) & 1) * STAGE_B;
            const size_t koff = (size_t)(c + 1) * 32;
            #pragma unroll
            for (int i = 0; i < 8; ++i) cp16(sd + doff[i], gsrc[i] + koff);
            cp_commit();
        }
        const uint32_t sb = su + (c & 1) * STAGE_B;
        const uint32_t aBase = sb + (wm0 + a_rl) * 80 + a_ch;      // + plane + im*16*80 + kk*32
        const uint32_t bBase = sb + (wn0 + b_rl) * 80;             // + plane + kk*32 + p*16

        #pragma unroll
        for (int kk = 0; kk < 2; ++kk) {
            const uint32_t kO = kk * 32;
            uint32_t a[4][4], b0[4], b1[4];
            // A_hi
            #pragma unroll
            for (int im = 0; im < 4; ++im)
                ldsm4(a[im], aBase + 0 * PLANE_B + im * (16 * 80) + kO);
            // B_lo
            ldsm4(b0, bBase + 3 * PLANE_B + kO);
            ldsm4(b1, bBase + 3 * PLANE_B + kO + 16);
            #pragma unroll
            for (int im = 0; im < 4; ++im)
                #pragma unroll
                for (int in = 0; in < 4; ++in)
                    mma16816(acc[im][in], a[im], b0[in], b1[in]);
            // B_hi
            ldsm4(b0, bBase + 2 * PLANE_B + kO);
            ldsm4(b1, bBase + 2 * PLANE_B + kO + 16);
            #pragma unroll
            for (int im = 0; im < 4; ++im)
                #pragma unroll
                for (int in = 0; in < 4; ++in)
                    mma16816(acc[im][in], a[im], b0[in], b1[in]);
            // A_lo
            #pragma unroll
            for (int im = 0; im < 4; ++im)
                ldsm4(a[im], aBase + 1 * PLANE_B + im * (16 * 80) + kO);
            #pragma unroll
            for (int im = 0; im < 4; ++im)
                #pragma unroll
                for (int in = 0; in < 4; ++in)
                    mma16816(acc[im][in], a[im], b0[in], b1[in]);
        }
    }

    // ---- epilogue ----
    const int mbase = bm0 + wm0 + (lane >> 2);
    const int nbase = bn0 + wn0 + (lane & 3) * 2;
    #pragma unroll
    for (int im = 0; im < 4; ++im) {
        #pragma unroll
        for (int in = 0; in < 4; ++in) {
            const float* d = acc[im][in];
            const int n0 = nbase + in * 8;
            if (FINAL) {
                const int m0 = mbase + im * 16;
                float2 v0, v1;
                v0.x = d[0] * alpha + bias[n0];
                v0.y = d[1] * alpha + bias[n0 + 1];
                v1.x = d[2] * alpha + bias[n0];
                v1.y = d[3] * alpha + bias[n0 + 1];
                *(float2*)(Cf + (size_t)m0 * Ntot + n0)       = v0;
                *(float2*)(Cf + (size_t)(m0 + 8) * Ntot + n0) = v1;
            } else {
                const float bz0 = bias ? bias[n0]     : 0.0f;
                const float bz1 = bias ? bias[n0 + 1] : 0.0f;
                #pragma unroll
                for (int j = 0; j < 4; ++j) {
                    const int m = mbase + im * 16 + (j >> 1) * 8;
                    const int n = n0 + (j & 1);
                    float v = d[j] * alpha + ((j & 1) ? bz1 : bz0);
                    __nv_bfloat16 h = __float2bfloat16(v);
                    __nv_bfloat16 l = __float2bfloat16(v - __bfloat162float(h));
                    size_t o = (size_t)n * Mtot + m;
                    Ch[o] = h;
                    Cl[o] = l;
                }
            }
        }
    }
}

// ---------------- preprocessing ----------------
__global__ void split_kernel(const float* __restrict__ in,
                             __nv_bfloat16* __restrict__ hi,
                             __nv_bfloat16* __restrict__ lo, int n)
{
    int i = (blockIdx.x * blockDim.x + threadIdx.x) * 4;
    if (i >= n) return;
    float4 v = *(const float4*)(in + i);
    float f[4] = {v.x, v.y, v.z, v.w};
    __nv_bfloat16 h[4], l[4];
    #pragma unroll
    for (int j = 0; j < 4; ++j) {
        h[j] = __float2bfloat16(f[j]);
        l[j] = __float2bfloat16(f[j] - __bfloat162float(h[j]));
    }
    *reinterpret_cast<__nv_bfloat162*>(hi + i)     = __halves2bfloat162(h[0], h[1]);
    *reinterpret_cast<__nv_bfloat162*>(hi + i + 2) = __halves2bfloat162(h[2], h[3]);
    *reinterpret_cast<__nv_bfloat162*>(lo + i)     = __halves2bfloat162(l[0], l[1]);
    *reinterpret_cast<__nv_bfloat162*>(lo + i + 2) = __halves2bfloat162(l[2], l[3]);
}

__global__ void transpose_split_kernel(const float* __restrict__ in,
                                       __nv_bfloat16* __restrict__ hi,
                                       __nv_bfloat16* __restrict__ lo,
                                       int rows, int cols)
{
    __shared__ float t[32][33];
    int bx = blockIdx.x * 32, by = blockIdx.y * 32;
    int tx = threadIdx.x, ty = threadIdx.y;  // 32 x 8
    #pragma unroll
    for (int j = 0; j < 32; j += 8)
        t[ty + j][tx] = in[(size_t)(by + ty + j) * cols + bx + tx];
    __syncthreads();
    #pragma unroll
    for (int j = 0; j < 32; j += 8) {
        float v = t[tx][ty + j];
        size_t o = (size_t)(bx + ty + j) * rows + by + tx;
        __nv_bfloat16 h = __float2bfloat16(v);
        hi[o] = h;
        lo[o] = __float2bfloat16(v - __bfloat162float(h));
    }
}

__global__ void rbias_kernel(const float* __restrict__ bq,
                             const __nv_bfloat16* __restrict__ MTh,
                             const __nv_bfloat16* __restrict__ MTl,
                             float* __restrict__ r, float scale)
{
    int warp = (blockIdx.x * blockDim.x + threadIdx.x) >> 5;
    int lane = threadIdx.x & 31;
    if (warp >= D_DIM) return;
    float s = 0.0f;
    for (int i = lane; i < D_DIM; i += 32)
        s += bq[i] * (__bfloat162float(MTh[(size_t)warp * D_DIM + i]) +
                      __bfloat162float(MTl[(size_t)warp * D_DIM + i]));
    #pragma unroll
    for (int o = 16; o; o >>= 1) s += __shfl_xor_sync(0xFFFFFFFFu, s, o);
    if (lane == 0) r[warp] = s * scale;
}

// ---------------- launcher ----------------
extern "C" void kernel_launch(void* const* d_in, const int* in_sizes, int n_in,
                              void* d_out, int out_size)
{
    const float* x  = (const float*)d_in[0];
    const float* Wq = (const float*)d_in[1];
    const float* bq = (const float*)d_in[2];
    const float* Wk = (const float*)d_in[3];
    const float* bk = (const float*)d_in[4];
    const float* Wv = (const float*)d_in[5];
    const float* bv = (const float*)d_in[6];
    float* out = (float*)d_out;

    __nv_bfloat16 *x_hi, *x_lo, *wk_hi, *wk_lo, *wv_hi, *wv_lo, *wqT_hi, *wqT_lo;
    __nv_bfloat16 *kt_hi, *kt_lo, *vt_hi, *vt_lo, *mt_hi, *mt_lo, *pt_hi, *pt_lo;
    float* r;
    cudaGetSymbolAddress((void**)&x_hi, g_x_hi);   cudaGetSymbolAddress((void**)&x_lo, g_x_lo);
    cudaGetSymbolAddress((void**)&wk_hi, g_wk_hi); cudaGetSymbolAddress((void**)&wk_lo, g_wk_lo);
    cudaGetSymbolAddress((void**)&wv_hi, g_wv_hi); cudaGetSymbolAddress((void**)&wv_lo, g_wv_lo);
    cudaGetSymbolAddress((void**)&wqT_hi, g_wqT_hi); cudaGetSymbolAddress((void**)&wqT_lo, g_wqT_lo);
    cudaGetSymbolAddress((void**)&kt_hi, g_kt_hi); cudaGetSymbolAddress((void**)&kt_lo, g_kt_lo);
    cudaGetSymbolAddress((void**)&vt_hi, g_vt_hi); cudaGetSymbolAddress((void**)&vt_lo, g_vt_lo);
    cudaGetSymbolAddress((void**)&mt_hi, g_mt_hi); cudaGetSymbolAddress((void**)&mt_lo, g_mt_lo);
    cudaGetSymbolAddress((void**)&pt_hi, g_pt_hi); cudaGetSymbolAddress((void**)&pt_lo, g_pt_lo);
    cudaGetSymbolAddress((void**)&r, g_r);

    cudaFuncSetAttribute(gemm_mma<false>, cudaFuncAttributeMaxDynamicSharedMemorySize, SMEM_DYN);
    cudaFuncSetAttribute(gemm_mma<true>,  cudaFuncAttributeMaxDynamicSharedMemorySize, SMEM_DYN);

    const float scale = 1.0f / sqrtf((float)D_DIM);
    dim3 blk(256);
    dim3 gridND(D_DIM / 128, N_TOK / 128);  // (16, 32)
    dim3 gridDD(D_DIM / 128, D_DIM / 128);  // (16, 16)

    split_kernel<<<(N_TOK * D_DIM / 4) / 256, 256>>>(x, x_hi, x_lo, N_TOK * D_DIM);
    split_kernel<<<(D_DIM * D_DIM / 4) / 256, 256>>>(Wk, wk_hi, wk_lo, D_DIM * D_DIM);
    split_kernel<<<(D_DIM * D_DIM / 4) / 256, 256>>>(Wv, wv_hi, wv_lo, D_DIM * D_DIM);
    transpose_split_kernel<<<dim3(D_DIM / 32, D_DIM / 32), dim3(32, 8)>>>(Wq, wqT_hi, wqT_lo, D_DIM, D_DIM);

    // 1) Kt = (x @ Wk^T + bk)^T
    gemm_mma<false><<<gridND, blk, SMEM_DYN>>>(
        x_hi, x_lo, wk_hi, wk_lo, bk, kt_hi, kt_lo, nullptr, N_TOK, D_DIM, D_DIM, 1.0f);
    // 2) Vt = (x @ Wv^T + bv)^T
    gemm_mma<false><<<gridND, blk, SMEM_DYN>>>(
        x_hi, x_lo, wv_hi, wv_lo, bv, vt_hi, vt_lo, nullptr, N_TOK, D_DIM, D_DIM, 1.0f);
    // 3) MT = (K^T V)^T   (K dim = N_TOK)
    gemm_mma<false><<<gridDD, blk, SMEM_DYN>>>(
        kt_hi, kt_lo, vt_hi, vt_lo, nullptr, mt_hi, mt_lo, nullptr, D_DIM, D_DIM, N_TOK, 1.0f);
    // r = scale * M^T bq
    rbias_kernel<<<D_DIM / 8, 256>>>(bq, mt_hi, mt_lo, r, scale);
    // 4) PT = (scale * Wq^T M)^T
    gemm_mma<false><<<gridDD, blk, SMEM_DYN>>>(
        wqT_hi, wqT_lo, mt_hi, mt_lo, nullptr, pt_hi, pt_lo, nullptr, D_DIM, D_DIM, D_DIM, scale);
    // 5) out = x @ P + r
    gemm_mma<true><<<gridND, blk, SMEM_DYN>>>(
        x_hi, x_lo, pt_hi, pt_lo, r, nullptr, nullptr, out, N_TOK, D_DIM, D_DIM, 1.0f);
}

// round 4
// speedup vs baseline: 3.0628x; 1.3023x over previous
#include <cuda_runtime.h>
#include <cuda_bf16.h>
#include <math.h>
#include <stdint.h>

#define D_DIM 2048
#define N_TOK 4096

// ---------------- device scratch (allocation-free rule) ----------------
__device__ __align__(128) __nv_bfloat16 g_xT_hi[(size_t)D_DIM * N_TOK];
__device__ __align__(128) __nv_bfloat16 g_xT_lo[(size_t)D_DIM * N_TOK];
__device__ __align__(128) __nv_bfloat16 g_x_hi [(size_t)N_TOK * D_DIM];
__device__ __align__(128) __nv_bfloat16 g_x_lo [(size_t)N_TOK * D_DIM];
__device__ __align__(128) __nv_bfloat16 g_wqT_hi[(size_t)D_DIM * D_DIM];
__device__ __align__(128) __nv_bfloat16 g_wqT_lo[(size_t)D_DIM * D_DIM];
__device__ __align__(128) __nv_bfloat16 g_wkT_hi[(size_t)D_DIM * D_DIM];
__device__ __align__(128) __nv_bfloat16 g_wkT_lo[(size_t)D_DIM * D_DIM];
__device__ __align__(128) __nv_bfloat16 g_wv_hi[(size_t)D_DIM * D_DIM];
__device__ __align__(128) __nv_bfloat16 g_wv_lo[(size_t)D_DIM * D_DIM];
__device__ __align__(128) __nv_bfloat16 g_g_hi [(size_t)D_DIM * D_DIM];
__device__ __align__(128) __nv_bfloat16 g_g_lo [(size_t)D_DIM * D_DIM];
__device__ __align__(128) __nv_bfloat16 g_t1_hi[(size_t)D_DIM * D_DIM];
__device__ __align__(128) __nv_bfloat16 g_t1_lo[(size_t)D_DIM * D_DIM];
__device__ __align__(128) __nv_bfloat16 g_t2_hi[(size_t)D_DIM * D_DIM];
__device__ __align__(128) __nv_bfloat16 g_t2_lo[(size_t)D_DIM * D_DIM];
__device__ __align__(128) __nv_bfloat16 g_pT_hi[(size_t)D_DIM * D_DIM];
__device__ __align__(128) __nv_bfloat16 g_pT_lo[(size_t)D_DIM * D_DIM];
__device__ float g_part[16 * D_DIM];
__device__ float g_u[D_DIM], g_w1[D_DIM], g_w2[D_DIM];
__device__ float g_v1[D_DIM], g_v2[D_DIM], g_v3[D_DIM], g_r[D_DIM];
__device__ float g_sc[2];

// ---------------- helpers ----------------
__device__ __forceinline__ uint32_t s2u(const void* p) {
    uint32_t a;
    asm("{ .reg .u64 t; cvta.to.shared.u64 t, %1; cvt.u32.u64 %0, t; }" : "=r"(a) : "l"(p));
    return a;
}
__device__ __forceinline__ void cp16(uint32_t dst, const void* src) {
    asm volatile("cp.async.cg.shared.global [%0], [%1], 16;" :: "r"(dst), "l"(src) : "memory");
}
__device__ __forceinline__ void cp_commit() {
    asm volatile("cp.async.commit_group;" ::: "memory");
}
template<int N>
__device__ __forceinline__ void cp_wait() {
    asm volatile("cp.async.wait_group %0;" :: "n"(N) : "memory");
}
__device__ __forceinline__ void ldsm4(uint32_t* r, uint32_t addr) {
    asm volatile("ldmatrix.sync.aligned.m8n8.x4.shared.b16 {%0,%1,%2,%3}, [%4];"
                 : "=r"(r[0]), "=r"(r[1]), "=r"(r[2]), "=r"(r[3]) : "r"(addr));
}
__device__ __forceinline__ void mma16816(float* d, const uint32_t* a, uint32_t b0, uint32_t b1) {
    asm volatile(
        "mma.sync.aligned.m16n8k16.row.col.f32.bf16.bf16.f32 "
        "{%0,%1,%2,%3}, {%4,%5,%6,%7}, {%8,%9}, {%0,%1,%2,%3};"
        : "+f"(d[0]), "+f"(d[1]), "+f"(d[2]), "+f"(d[3])
        : "r"(a[0]), "r"(a[1]), "r"(a[2]), "r"(a[3]), "r"(b0), "r"(b1));
}

// ---------------- split-bf16 HMMA GEMM ----------------
// C[m,n] = alpha * sum_k (Ah+Al)[m,k]*(Bh+Bl)[n,k]  (drops lo*lo)
// MODE 0 NORM : Ch/Cl[m*Ntot+n] = split(val)
// MODE 1 SYM  : NORM + mirror Ch/Cl[n*Ntot+m]; 1D grid of 136 upper-tri tiles
// MODE 2 TRANS: Ch/Cl[n*Mtot+m] = split(val + cA[m]cB[n] + cC[m]cD[n])
// MODE 3 FINAL: Cf[m*Ntot+n]    = val + biascol[n]   (fp32)
#define PLANE_B 10240
#define STAGE_B 40960
static const int SMEM_DYN = 2 * STAGE_B;

template<int MODE>
__global__ void __launch_bounds__(256, 2) gemm_mma(
    const __nv_bfloat16* __restrict__ Ah, const __nv_bfloat16* __restrict__ Al,
    const __nv_bfloat16* __restrict__ Bh, const __nv_bfloat16* __restrict__ Bl,
    __nv_bfloat16* __restrict__ Ch, __nv_bfloat16* __restrict__ Cl,
    float* __restrict__ Cf,
    const float* __restrict__ cA, const float* __restrict__ cB,
    const float* __restrict__ cC, const float* __restrict__ cD,
    const float* __restrict__ biascol,
    int Mtot, int Ntot, int Kd, float alpha)
{
    extern __shared__ char dyn[];
    const uint32_t su = s2u(dyn);
    const int tid  = threadIdx.x;
    const int wid  = tid >> 5, lane = tid & 31;

    int bxt, byt;
    if (MODE == 1) {
        int idx = blockIdx.x, by = 0;
        while (idx >= 16 - by) { idx -= 16 - by; ++by; }
        byt = by; bxt = by + idx;           // upper triangle incl diagonal
    } else {
        bxt = blockIdx.x; byt = blockIdx.y;
    }
    const int bm0 = byt * 128;
    const int bn0 = bxt * 128;
    const int wm0 = (wid & 1) * 64;
    const int wn0 = (wid >> 1) * 32;

    // cp.async schedule: 2048 16B transfers / 256 threads = 8 each
    const __nv_bfloat16* gsrc[8];
    uint32_t doff[8];
    #pragma unroll
    for (int i = 0; i < 8; ++i) {
        int idx   = i * 256 + tid;
        int plane = idx >> 9;
        int row   = (idx >> 2) & 127;
        int seg   = idx & 3;
        const __nv_bfloat16* base =
            (plane == 0) ? Ah : (plane == 1) ? Al : (plane == 2) ? Bh : Bl;
        int grow = (plane < 2 ? bm0 : bn0) + row;
        gsrc[i] = base + (size_t)grow * Kd + seg * 8;
        doff[i] = (uint32_t)(plane * PLANE_B + row * 80 + seg * 16);
    }

    const int NC = Kd / 32;
    #pragma unroll
    for (int i = 0; i < 8; ++i) cp16(su + doff[i], gsrc[i]);
    cp_commit();

    float acc[4][4][4];
    #pragma unroll
    for (int im = 0; im < 4; ++im)
        #pragma unroll
        for (int in = 0; in < 4; ++in)
            #pragma unroll
            for (int j = 0; j < 4; ++j) acc[im][in][j] = 0.0f;

    const int a_rl = ((lane >> 3) & 1) * 8 + (lane & 7);
    const int a_ch = ((lane >> 4) & 1) * 16;
    const int b_rl = lane;

    for (int c = 0; c < NC; ++c) {
        cp_wait<0>();
        __syncthreads();
        if (c + 1 < NC) {
            const uint32_t sd = su + ((c + 1) & 1) * STAGE_B;
            const size_t koff = (size_t)(c + 1) * 32;
            #pragma unroll
            for (int i = 0; i < 8; ++i) cp16(sd + doff[i], gsrc[i] + koff);
            cp_commit();
        }
        const uint32_t sb = su + (c & 1) * STAGE_B;
        const uint32_t aBase = sb + (wm0 + a_rl) * 80 + a_ch;
        const uint32_t bBase = sb + (wn0 + b_rl) * 80;

        #pragma unroll
        for (int kk = 0; kk < 2; ++kk) {
            const uint32_t kO = kk * 32;
            uint32_t a[4][4], b0[4], b1[4];
            #pragma unroll
            for (int im = 0; im < 4; ++im)
                ldsm4(a[im], aBase + 0 * PLANE_B + im * (16 * 80) + kO);
            ldsm4(b0, bBase + 3 * PLANE_B + kO);
            ldsm4(b1, bBase + 3 * PLANE_B + kO + 16);
            #pragma unroll
            for (int im = 0; im < 4; ++im)
                #pragma unroll
                for (int in = 0; in < 4; ++in)
                    mma16816(acc[im][in], a[im], b0[in], b1[in]);
            ldsm4(b0, bBase + 2 * PLANE_B + kO);
            ldsm4(b1, bBase + 2 * PLANE_B + kO + 16);
            #pragma unroll
            for (int im = 0; im < 4; ++im)
                #pragma unroll
                for (int in = 0; in < 4; ++in)
                    mma16816(acc[im][in], a[im], b0[in], b1[in]);
            #pragma unroll
            for (int im = 0; im < 4; ++im)
                ldsm4(a[im], aBase + 1 * PLANE_B + im * (16 * 80) + kO);
            #pragma unroll
            for (int im = 0; im < 4; ++im)
                #pragma unroll
                for (int in = 0; in < 4; ++in)
                    mma16816(acc[im][in], a[im], b0[in], b1[in]);
        }
    }

    // ---- epilogue ----
    const int mbase = bm0 + wm0 + (lane >> 2);
    const int nbase = bn0 + wn0 + (lane & 3) * 2;
    #pragma unroll
    for (int im = 0; im < 4; ++im) {
        #pragma unroll
        for (int in = 0; in < 4; ++in) {
            const float* d = acc[im][in];
            const int n0 = nbase + in * 8;
            if (MODE == 3) {
                const int m0 = mbase + im * 16;
                float2 v0, v1;
                v0.x = d[0] * alpha + biascol[n0];
                v0.y = d[1] * alpha + biascol[n0 + 1];
                v1.x = d[2] * alpha + biascol[n0];
                v1.y = d[3] * alpha + biascol[n0 + 1];
                *(float2*)(Cf + (size_t)m0 * Ntot + n0)       = v0;
                *(float2*)(Cf + (size_t)(m0 + 8) * Ntot + n0) = v1;
            } else {
                #pragma unroll
                for (int j = 0; j < 4; ++j) {
                    const int m = mbase + im * 16 + (j >> 1) * 8;
                    const int n = n0 + (j & 1);
                    float v = d[j] * alpha;
                    if (MODE == 2) v += cA[m] * cB[n] + cC[m] * cD[n];
                    __nv_bfloat16 h = __float2bfloat16(v);
                    __nv_bfloat16 l = __float2bfloat16(v - __bfloat162float(h));
                    if (MODE == 0) {
                        size_t o = (size_t)m * Ntot + n;
                        Ch[o] = h; Cl[o] = l;
                    } else if (MODE == 1) {
                        size_t o1 = (size_t)m * Ntot + n;
                        size_t o2 = (size_t)n * Ntot + m;
                        Ch[o1] = h; Cl[o1] = l;
                        Ch[o2] = h; Cl[o2] = l;
                    } else { // TRANS
                        size_t o = (size_t)n * Mtot + m;
                        Ch[o] = h; Cl[o] = l;
                    }
                }
            }
        }
    }
}

// ---------------- preprocessing ----------------
__global__ void split_kernel(const float* __restrict__ in,
                             __nv_bfloat16* __restrict__ hi,
                             __nv_bfloat16* __restrict__ lo, int n)
{
    int i = (blockIdx.x * blockDim.x + threadIdx.x) * 4;
    if (i >= n) return;
    float4 v = *(const float4*)(in + i);
    float f[4] = {v.x, v.y, v.z, v.w};
    __nv_bfloat16 h[4], l[4];
    #pragma unroll
    for (int j = 0; j < 4; ++j) {
        h[j] = __float2bfloat16(f[j]);
        l[j] = __float2bfloat16(f[j] - __bfloat162float(h[j]));
    }
    *reinterpret_cast<__nv_bfloat162*>(hi + i)     = __halves2bfloat162(h[0], h[1]);
    *reinterpret_cast<__nv_bfloat162*>(hi + i + 2) = __halves2bfloat162(h[2], h[3]);
    *reinterpret_cast<__nv_bfloat162*>(lo + i)     = __halves2bfloat162(l[0], l[1]);
    *reinterpret_cast<__nv_bfloat162*>(lo + i + 2) = __halves2bfloat162(l[2], l[3]);
}

// out[c*rows + r] = split(in[r*cols + c])
__global__ void transpose_split_kernel(const float* __restrict__ in,
                                       __nv_bfloat16* __restrict__ hi,
                                       __nv_bfloat16* __restrict__ lo,
                                       int rows, int cols)
{
    __shared__ float t[32][33];
    int bx = blockIdx.x * 32, by = blockIdx.y * 32;
    int tx = threadIdx.x, ty = threadIdx.y;  // 32 x 8
    #pragma unroll
    for (int j = 0; j < 32; j += 8)
        t[ty + j][tx] = in[(size_t)(by + ty + j) * cols + bx + tx];
    __syncthreads();
    #pragma unroll
    for (int j = 0; j < 32; j += 8) {
        float v = t[tx][ty + j];
        size_t o = (size_t)(bx + ty + j) * rows + by + tx;
        __nv_bfloat16 h = __float2bfloat16(v);
        hi[o] = h;
        lo[o] = __float2bfloat16(v - __bfloat162float(h));
    }
}

// ---------------- small vector ops (bias corrections, exact fp32) ----------------
// part[c*D + d] = sum over rows r in chunk c of (vec ? vec[r] : 1) * W[r*D + d]
__global__ void wpart_kernel(const float* __restrict__ W, const float* __restrict__ vec,
                             float* __restrict__ part, int R)
{
    int d = blockIdx.x * blockDim.x + threadIdx.x;
    int c = blockIdx.y;
    int chunk = R / 16;
    float s = 0.0f;
    for (int r = c * chunk; r < (c + 1) * chunk; ++r)
        s = fmaf(vec ? vec[r] : 1.0f, W[(size_t)r * D_DIM + d], s);
    part[c * D_DIM + d] = s;
}
// y[d] = alpha * sum_c part[c*D+d]
__global__ void wreduce_kernel(const float* __restrict__ part, float* __restrict__ y, float alpha)
{
    int d = blockIdx.x * blockDim.x + threadIdx.x;
    float s = 0.0f;
    #pragma unroll
    for (int c = 0; c < 16; ++c) s += part[c * D_DIM + d];
    y[d] = s * alpha;
}
// y[i] = sum_j W[i*D+j]*v[j] + addscale*add[i]   (warp per row)
__global__ void rowmv_kernel(const float* __restrict__ W, const float* __restrict__ v,
                             const float* __restrict__ add, float addscale,
                             float* __restrict__ y)
{
    int i = (blockIdx.x * blockDim.x + threadIdx.x) >> 5;
    int lane = threadIdx.x & 31;
    if (i >= D_DIM) return;
    float s = 0.0f;
    for (int j = lane; j < D_DIM; j += 32) s = fmaf(W[(size_t)i * D_DIM + j], v[j], s);
    #pragma unroll
    for (int o = 16; o; o >>= 1) s += __shfl_xor_sync(0xFFFFFFFFu, s, o);
    if (lane == 0) y[i] = s + (add ? addscale * add[i] : 0.0f);
}
// y[i] = alpha * sum_j (hi+lo)[i*D+j] * v[j]   (warp per row, split matrix)
__global__ void splitmv_kernel(const __nv_bfloat16* __restrict__ hi,
                               const __nv_bfloat16* __restrict__ lo,
                               const float* __restrict__ v,
                               float* __restrict__ y, float alpha)
{
    int i = (blockIdx.x * blockDim.x + threadIdx.x) >> 5;
    int lane = threadIdx.x & 31;
    if (i >= D_DIM) return;
    float s = 0.0f;
    for (int j = lane; j < D_DIM; j += 32)
        s = fmaf(__bfloat162float(hi[(size_t)i * D_DIM + j]) +
                 __bfloat162float(lo[(size_t)i * D_DIM + j]), v[j], s);
    #pragma unroll
    for (int o = 16; o; o >>= 1) s += __shfl_xor_sync(0xFFFFFFFFu, s, o);
    if (lane == 0) y[i] = s * alpha;
}
// sc[0] = dot(a,b); sc[1] = dot(c,d)
__global__ void dot2_kernel(const float* a, const float* b,
                            const float* c, const float* d, float* sc)
{
    __shared__ float red[256];
    int tid = threadIdx.x;
    float s = 0.0f;
    if (blockIdx.x == 0)
        for (int i = tid; i < D_DIM; i += 256) s = fmaf(a[i], b[i], s);
    else
        for (int i = tid; i < D_DIM; i += 256) s = fmaf(c[i], d[i], s);
    red[tid] = s;
    __syncthreads();
    for (int o = 128; o; o >>= 1) { if (tid < o) red[tid] += red[tid + o]; __syncthreads(); }
    if (tid == 0) sc[blockIdx.x] = red[0];
}
// r[i] = s*( sum_j Wv[i*D+j]*w2[j] + bv[i]*sc[0] + v3[i]*sc[1] )
__global__ void r_kernel(const float* __restrict__ Wv, const float* __restrict__ w2,
                         const float* __restrict__ bv, const float* __restrict__ v3,
                         const float* __restrict__ sc, float* __restrict__ r, float s)
{
    int i = (blockIdx.x * blockDim.x + threadIdx.x) >> 5;
    int lane = threadIdx.x & 31;
    if (i >= D_DIM) return;
    float acc = 0.0f;
    for (int j = lane; j < D_DIM; j += 32) acc = fmaf(Wv[(size_t)i * D_DIM + j], w2[j], acc);
    #pragma unroll
    for (int o = 16; o; o >>= 1) acc += __shfl_xor_sync(0xFFFFFFFFu, acc, o);
    if (lane == 0) r[i] = s * (acc + bv[i] * sc[0] + v3[i] * sc[1]);
}

// ---------------- launcher ----------------
extern "C" void kernel_launch(void* const* d_in, const int* in_sizes, int n_in,
                              void* d_out, int out_size)
{
    const float* x  = (const float*)d_in[0];
    const float* Wq = (const float*)d_in[1];
    const float* bq = (const float*)d_in[2];
    const float* Wk = (const float*)d_in[3];
    const float* bk = (const float*)d_in[4];
    const float* Wv = (const float*)d_in[5];
    const float* bv = (const float*)d_in[6];
    float* out = (float*)d_out;

    __nv_bfloat16 *xT_hi, *xT_lo, *x_hi, *x_lo, *wqT_hi, *wqT_lo, *wkT_hi, *wkT_lo;
    __nv_bfloat16 *wv_hi, *wv_lo, *gh, *gl, *t1h, *t1l, *t2h, *t2l, *pTh, *pTl;
    float *part, *u, *w1, *w2, *v1, *v2, *v3, *r, *sc;
    cudaGetSymbolAddress((void**)&xT_hi, g_xT_hi);  cudaGetSymbolAddress((void**)&xT_lo, g_xT_lo);
    cudaGetSymbolAddress((void**)&x_hi, g_x_hi);    cudaGetSymbolAddress((void**)&x_lo, g_x_lo);
    cudaGetSymbolAddress((void**)&wqT_hi, g_wqT_hi);cudaGetSymbolAddress((void**)&wqT_lo, g_wqT_lo);
    cudaGetSymbolAddress((void**)&wkT_hi, g_wkT_hi);cudaGetSymbolAddress((void**)&wkT_lo, g_wkT_lo);
    cudaGetSymbolAddress((void**)&wv_hi, g_wv_hi);  cudaGetSymbolAddress((void**)&wv_lo, g_wv_lo);
    cudaGetSymbolAddress((void**)&gh, g_g_hi);      cudaGetSymbolAddress((void**)&gl, g_g_lo);
    cudaGetSymbolAddress((void**)&t1h, g_t1_hi);    cudaGetSymbolAddress((void**)&t1l, g_t1_lo);
    cudaGetSymbolAddress((void**)&t2h, g_t2_hi);    cudaGetSymbolAddress((void**)&t2l, g_t2_lo);
    cudaGetSymbolAddress((void**)&pTh, g_pT_hi);    cudaGetSymbolAddress((void**)&pTl, g_pT_lo);
    cudaGetSymbolAddress((void**)&part, g_part);
    cudaGetSymbolAddress((void**)&u, g_u);   cudaGetSymbolAddress((void**)&w1, g_w1);
    cudaGetSymbolAddress((void**)&w2, g_w2); cudaGetSymbolAddress((void**)&v1, g_v1);
    cudaGetSymbolAddress((void**)&v2, g_v2); cudaGetSymbolAddress((void**)&v3, g_v3);
    cudaGetSymbolAddress((void**)&r, g_r);   cudaGetSymbolAddress((void**)&sc, g_sc);

    cudaFuncSetAttribute(gemm_mma<0>, cudaFuncAttributeMaxDynamicSharedMemorySize, SMEM_DYN);
    cudaFuncSetAttribute(gemm_mma<1>, cudaFuncAttributeMaxDynamicSharedMemorySize, SMEM_DYN);
    cudaFuncSetAttribute(gemm_mma<2>, cudaFuncAttributeMaxDynamicSharedMemorySize, SMEM_DYN);
    cudaFuncSetAttribute(gemm_mma<3>, cudaFuncAttributeMaxDynamicSharedMemorySize, SMEM_DYN);

    const float s = 1.0f / sqrtf((float)D_DIM);
    dim3 blk(256);

    // ---- operand preparation ----
    transpose_split_kernel<<<dim3(D_DIM / 32, N_TOK / 32), dim3(32, 8)>>>(x, xT_hi, xT_lo, N_TOK, D_DIM);
    split_kernel<<<(N_TOK * D_DIM / 4) / 256, 256>>>(x, x_hi, x_lo, N_TOK * D_DIM);
    transpose_split_kernel<<<dim3(D_DIM / 32, D_DIM / 32), dim3(32, 8)>>>(Wq, wqT_hi, wqT_lo, D_DIM, D_DIM);
    transpose_split_kernel<<<dim3(D_DIM / 32, D_DIM / 32), dim3(32, 8)>>>(Wk, wkT_hi, wkT_lo, D_DIM, D_DIM);
    split_kernel<<<(D_DIM * D_DIM / 4) / 256, 256>>>(Wv, wv_hi, wv_lo, D_DIM * D_DIM);

    // ---- bias-correction vectors (exact fp32; zeros in this dataset) ----
    wpart_kernel<<<dim3(D_DIM / 256, 16), 256>>>(x, nullptr, part, N_TOK);       // u partials
    wreduce_kernel<<<D_DIM / 256, 256>>>(part, u, 1.0f);                          // u = x^T 1
    wpart_kernel<<<dim3(D_DIM / 256, 16), 256>>>(Wk, bq, part, D_DIM);            // w1 partials
    wreduce_kernel<<<D_DIM / 256, 256>>>(part, w1, 1.0f);                         // w1 = Wk^T bq
    dot2_kernel<<<2, 256>>>(u, w1, bk, bq, sc);                                   // sc0=u.w1 sc1=bk.bq
    wpart_kernel<<<dim3(D_DIM / 256, 16), 256>>>(Wq, bk, part, D_DIM);            // v2 partials
    wreduce_kernel<<<D_DIM / 256, 256>>>(part, v2, s);                            // v2 = s*Wq^T bk
    rowmv_kernel<<<D_DIM / 8, 256>>>(Wv, u, bv, (float)N_TOK, v3);                // v3 = Wv u + N bv

    // ---- GEMM chain ----
    // G = x^T x  (symmetric, 136 upper-tri tiles, mirror store)
    gemm_mma<1><<<136, blk, SMEM_DYN>>>(xT_hi, xT_lo, xT_hi, xT_lo,
        gh, gl, nullptr, nullptr, nullptr, nullptr, nullptr, nullptr,
        D_DIM, D_DIM, N_TOK, 1.0f);
    splitmv_kernel<<<D_DIM / 8, 256>>>(gh, gl, w1, w2, 1.0f);                     // w2 = G w1
    // T1 = Wq^T Wk
    gemm_mma<0><<<dim3(16, 16), blk, SMEM_DYN>>>(wqT_hi, wqT_lo, wkT_hi, wkT_lo,
        t1h, t1l, nullptr, nullptr, nullptr, nullptr, nullptr, nullptr,
        D_DIM, D_DIM, D_DIM, 1.0f);
    splitmv_kernel<<<D_DIM / 8, 256>>>(t1h, t1l, u, v1, s);                       // v1 = s*T1 u
    // T2 = T1 G   (B[n,k] = G[k,n] = G[n,k] by symmetry)
    gemm_mma<0><<<dim3(16, 16), blk, SMEM_DYN>>>(t1h, t1l, gh, gl,
        t2h, t2l, nullptr, nullptr, nullptr, nullptr, nullptr, nullptr,
        D_DIM, D_DIM, D_DIM, 1.0f);
    // P = s*T2 Wv^T + v1 bv^T + v2 v3^T   (store transposed-split pT)
    gemm_mma<2><<<dim3(16, 16), blk, SMEM_DYN>>>(t2h, t2l, wv_hi, wv_lo,
        pTh, pTl, nullptr, v1, bv, v2, v3, nullptr,
        D_DIM, D_DIM, D_DIM, s);
    // r = s*(Wv w2 + bv*sc0 + v3*sc1)
    r_kernel<<<D_DIM / 8, 256>>>(Wv, w2, bv, v3, sc, r, s);
    // out = x P + 1 r^T
    gemm_mma<3><<<dim3(16, 32), blk, SMEM_DYN>>>(x_hi, x_lo, pTh, pTl,
        nullptr, nullptr, out, nullptr, nullptr, nullptr, nullptr, r,
        N_TOK, D_DIM, D_DIM, 1.0f);
}